// round 4
// baseline (speedup 1.0000x reference)
#include <cuda_runtime.h>
#include <cstdint>

// ---------------------------------------------------------------------------
// Problem constants
// ---------------------------------------------------------------------------
#define BATCH     128
#define G_GROUPS  10000
#define NCH       3
#define KWIN      20
#define LATDIM    2000
#define GC        30000      // G_GROUPS * NCH
#define INPUT_LEN 200000     // G_GROUPS * KWIN

// GEMM1 K-split: 9 splits of 3344 (multiple of 16 -> aligned cp.async),
// last split clipped to 30000 (len 3248, also multiple of 16).
#define KSPLIT1      9
#define KSPLIT_LEN1  3344

// ---------------------------------------------------------------------------
// Device scratch (static __device__ arrays; no runtime allocation)
// ---------------------------------------------------------------------------
__device__ float g_h [BATCH * GC];                 // encoder conv output  (15.4 MB)
__device__ float g_zp[KSPLIT1 * BATCH * LATDIM];   // GEMM1 partials       ( 9.2 MB)
__device__ float g_z [BATCH * LATDIM];             // latent               ( 1.0 MB)
__device__ float g_d [BATCH * GC];                 // decoder FC output    (15.4 MB)

__device__ __forceinline__ float lrelu(float v) { return v > 0.f ? v : 0.1f * v; }

// ---------------------------------------------------------------------------
// Kernel 1: encoder grouped conv
//   g_h[b, g*3+c] = lrelu(dot(x[b, g*20 : g*20+20], enc_w[g,c,:]) + enc_b[g,c])
// ---------------------------------------------------------------------------
__global__ void enc_conv_kernel(const float* __restrict__ x,
                                const float* __restrict__ w,
                                const float* __restrict__ bias)
{
    int idx = blockIdx.x * blockDim.x + threadIdx.x;
    if (idx >= BATCH * G_GROUPS) return;
    int b = idx / G_GROUPS;
    int g = idx - b * G_GROUPS;

    const float4* xp = reinterpret_cast<const float4*>(x + (size_t)b * INPUT_LEN + (size_t)g * KWIN);
    float xr[KWIN];
#pragma unroll
    for (int i = 0; i < 5; ++i) {
        float4 v = __ldg(xp + i);
        xr[4*i+0] = v.x; xr[4*i+1] = v.y; xr[4*i+2] = v.z; xr[4*i+3] = v.w;
    }
    const float4* wp = reinterpret_cast<const float4*>(w + (size_t)g * (NCH * KWIN));
    float wr[NCH * KWIN];
#pragma unroll
    for (int i = 0; i < 15; ++i) {
        float4 v = __ldg(wp + i);
        wr[4*i+0] = v.x; wr[4*i+1] = v.y; wr[4*i+2] = v.z; wr[4*i+3] = v.w;
    }
    float acc[NCH];
#pragma unroll
    for (int c = 0; c < NCH; ++c) acc[c] = __ldg(bias + (size_t)g * NCH + c);
#pragma unroll
    for (int c = 0; c < NCH; ++c)
#pragma unroll
        for (int k = 0; k < KWIN; ++k)
            acc[c] = fmaf(xr[k], wr[c * KWIN + k], acc[c]);

    float* hp = g_h + (size_t)b * GC + (size_t)g * NCH;
#pragma unroll
    for (int c = 0; c < NCH; ++c) hp[c] = lrelu(acc[c]);
}

// ---------------------------------------------------------------------------
// TF32 tensor-core GEMM:  C[128, N] = A[128, K] * B[N, K]^T   ("TN", K-contig)
//   CTA tile 128x128, K-chunk 16, double-buffered cp.async.
//   EPI=0: write raw partial (per-k-split buffer);  EPI=1: +bias, leaky-relu.
//   All k offsets reaching cp.async are multiples of 4 floats (16B aligned).
// ---------------------------------------------------------------------------
#define BM 128
#define BN 128
#define BK 16
#define SSTR 20          // BK + 4 pad: conflict-free fragment LDS
#define GEMM_THREADS 256

__device__ __forceinline__ uint32_t f2tf(float f) {
    uint32_t r;
    asm("cvt.rna.tf32.f32 %0, %1;" : "=r"(r) : "f"(f));
    return r;
}

__device__ __forceinline__ void cp16(float* sdst, const float* gsrc, int bytes) {
    uint32_t sa = static_cast<uint32_t>(__cvta_generic_to_shared(sdst));
    asm volatile("cp.async.cg.shared.global [%0], [%1], 16, %2;\n"
                 :: "r"(sa), "l"(gsrc), "r"(bytes));
}

template <int EPI>
__global__ void __launch_bounds__(GEMM_THREADS, 2)
gemm_tf32_kernel(const float* __restrict__ A, int ldA,
                 const float* __restrict__ Bm, int ldB,
                 float* __restrict__ Cbase, int ldC, int cSplitStride,
                 const float* __restrict__ bias,
                 int N, int K, int kSplitLen)
{
    __shared__ __align__(16) float As[2][BM * SSTR];
    __shared__ __align__(16) float Bs[2][BN * SSTR];

    const int tid  = threadIdx.x;
    const int n0   = blockIdx.x * BN;
    const int kBeg = blockIdx.y * kSplitLen;
    const int kEnd = min(K, kBeg + kSplitLen);
    float* C = Cbase + (size_t)blockIdx.y * cSplitStride;

    const int loadRow = tid >> 2;        // 0..63
    const int loadKq  = tid & 3;         // which 4-float chunk of the k-row

    const int warp  = tid >> 5;
    const int lane  = tid & 31;
    const int g     = lane >> 2;
    const int tig   = lane & 3;
    const int wMoff = (warp & 3) * 32;   // 4 warps along M
    const int wNoff = (warp >> 2) * 64;  // 2 warps along N

    float acc[2][8][4];
#pragma unroll
    for (int mt = 0; mt < 2; ++mt)
#pragma unroll
        for (int nt = 0; nt < 8; ++nt)
#pragma unroll
            for (int i = 0; i < 4; ++i) acc[mt][nt][i] = 0.f;

    auto load_stage = [&](int st, int k0) {
#pragma unroll
        for (int j = 0; j < 2; ++j) {               // A tile: 128 x 16
            int row = loadRow + 64 * j;
            int k   = k0 + loadKq * 4;
            int bytes = (kEnd - k) * 4;             // always 0 or >=16 here
            bytes = bytes < 0 ? 0 : (bytes > 16 ? 16 : bytes);
            const float* gp = bytes > 0 ? (A + (size_t)row * ldA + k) : A;
            cp16(&As[st][row * SSTR + loadKq * 4], gp, bytes);
        }
#pragma unroll
        for (int j = 0; j < 2; ++j) {               // B tile: 128 x 16
            int row = loadRow + 64 * j;
            int n   = n0 + row;
            int k   = k0 + loadKq * 4;
            int bytes = (kEnd - k) * 4;
            bytes = bytes < 0 ? 0 : (bytes > 16 ? 16 : bytes);
            if (n >= N) bytes = 0;
            const float* gp = bytes > 0 ? (Bm + (size_t)n * ldB + k) : Bm;
            cp16(&Bs[st][row * SSTR + loadKq * 4], gp, bytes);
        }
        asm volatile("cp.async.commit_group;\n" ::: "memory");
    };

    const int nChunks = (kEnd - kBeg + BK - 1) / BK;
    load_stage(0, kBeg);

#pragma unroll 1
    for (int c = 0; c < nChunks; ++c) {
        if (c + 1 < nChunks) {
            load_stage((c + 1) & 1, kBeg + (c + 1) * BK);
            asm volatile("cp.async.wait_group 1;\n" ::: "memory");
        } else {
            asm volatile("cp.async.wait_group 0;\n" ::: "memory");
        }
        __syncthreads();

        const float* As_ = As[c & 1];
        const float* Bs_ = Bs[c & 1];
#pragma unroll
        for (int ks = 0; ks < BK / 8; ++ks) {
            const int kb = ks * 8;
            uint32_t af[2][4];
#pragma unroll
            for (int mt = 0; mt < 2; ++mt) {
                int r = wMoff + mt * 16 + g;
                af[mt][0] = f2tf(As_[(r    ) * SSTR + kb + tig    ]);
                af[mt][1] = f2tf(As_[(r + 8) * SSTR + kb + tig    ]);
                af[mt][2] = f2tf(As_[(r    ) * SSTR + kb + tig + 4]);
                af[mt][3] = f2tf(As_[(r + 8) * SSTR + kb + tig + 4]);
            }
            uint32_t bf[8][2];
#pragma unroll
            for (int nt = 0; nt < 8; ++nt) {
                int rn = wNoff + nt * 8 + g;
                bf[nt][0] = f2tf(Bs_[rn * SSTR + kb + tig    ]);
                bf[nt][1] = f2tf(Bs_[rn * SSTR + kb + tig + 4]);
            }
#pragma unroll
            for (int mt = 0; mt < 2; ++mt)
#pragma unroll
                for (int nt = 0; nt < 8; ++nt) {
                    asm volatile(
                        "mma.sync.aligned.m16n8k8.row.col.f32.tf32.tf32.f32 "
                        "{%0,%1,%2,%3}, {%4,%5,%6,%7}, {%8,%9}, {%0,%1,%2,%3};\n"
                        : "+f"(acc[mt][nt][0]), "+f"(acc[mt][nt][1]),
                          "+f"(acc[mt][nt][2]), "+f"(acc[mt][nt][3])
                        : "r"(af[mt][0]), "r"(af[mt][1]), "r"(af[mt][2]), "r"(af[mt][3]),
                          "r"(bf[nt][0]), "r"(bf[nt][1]));
                }
        }
        __syncthreads();
    }

    // Epilogue: c0,c1 -> (row, 2*tig[+1]); c2,c3 -> (row+8, ...)
#pragma unroll
    for (int mt = 0; mt < 2; ++mt) {
        int row0 = wMoff + mt * 16 + g;
#pragma unroll
        for (int nt = 0; nt < 8; ++nt) {
            int col = n0 + wNoff + nt * 8 + 2 * tig;
#pragma unroll
            for (int hh = 0; hh < 2; ++hh) {
                int row = row0 + 8 * hh;
#pragma unroll
                for (int q = 0; q < 2; ++q) {
                    int cc = col + q;
                    if (cc < N) {
                        float v = acc[mt][nt][hh * 2 + q];
                        if (EPI == 1) {
                            v += __ldg(bias + cc);
                            v = v > 0.f ? v : 0.1f * v;
                        }
                        C[(size_t)row * ldC + cc] = v;
                    }
                }
            }
        }
    }
}

// ---------------------------------------------------------------------------
// Kernel 3: reduce GEMM1 k-split partials + bias + leaky-relu -> g_z
// ---------------------------------------------------------------------------
__global__ void reduce_z_kernel(const float* __restrict__ bias)
{
    int i = blockIdx.x * blockDim.x + threadIdx.x;
    if (i >= BATCH * LATDIM) return;
    float s = __ldg(bias + (i % LATDIM));
#pragma unroll
    for (int p = 0; p < KSPLIT1; ++p) s += g_zp[(size_t)p * (BATCH * LATDIM) + i];
    g_z[i] = s > 0.f ? s : 0.1f * s;
}

// ---------------------------------------------------------------------------
// Kernel 5: decoder grouped conv-transpose + sigmoid
//   out[b, g*20+k] = sigmoid(sum_c g_d[b,g*3+c] * dec_w[g,c,k] + dec_b[g])
// ---------------------------------------------------------------------------
__global__ void dec_conv_kernel(const float* __restrict__ w,
                                const float* __restrict__ bias,
                                float* __restrict__ out)
{
    int idx = blockIdx.x * blockDim.x + threadIdx.x;
    if (idx >= BATCH * G_GROUPS) return;
    int b = idx / G_GROUPS;
    int g = idx - b * G_GROUPS;

    const float* dp = g_d + (size_t)b * GC + (size_t)g * NCH;
    float d0 = __ldg(dp + 0), d1 = __ldg(dp + 1), d2 = __ldg(dp + 2);

    float wr[NCH * KWIN];
    const float4* wp = reinterpret_cast<const float4*>(w + (size_t)g * (NCH * KWIN));
#pragma unroll
    for (int i = 0; i < 15; ++i) {
        float4 v = __ldg(wp + i);
        wr[4*i+0] = v.x; wr[4*i+1] = v.y; wr[4*i+2] = v.z; wr[4*i+3] = v.w;
    }
    float bg = __ldg(bias + g);

    float4* op = reinterpret_cast<float4*>(out + (size_t)b * INPUT_LEN + (size_t)g * KWIN);
#pragma unroll
    for (int i = 0; i < 5; ++i) {
        float4 o;
        float* of = reinterpret_cast<float*>(&o);
#pragma unroll
        for (int j = 0; j < 4; ++j) {
            int k = 4 * i + j;
            float v = bg;
            v = fmaf(d0, wr[k], v);
            v = fmaf(d1, wr[KWIN + k], v);
            v = fmaf(d2, wr[2 * KWIN + k], v);
            of[j] = 1.f / (1.f + __expf(-v));
        }
        op[i] = o;
    }
}

// ---------------------------------------------------------------------------
// Launch (graph-capturable: kernel launches only)
// ---------------------------------------------------------------------------
extern "C" void kernel_launch(void* const* d_in, const int* in_sizes, int n_in,
                              void* d_out, int out_size)
{
    const float* x     = (const float*)d_in[0];
    const float* enc_w = (const float*)d_in[1];
    const float* enc_b = (const float*)d_in[2];
    const float* efc_w = (const float*)d_in[3];
    const float* efc_b = (const float*)d_in[4];
    const float* dfc_w = (const float*)d_in[5];
    const float* dfc_b = (const float*)d_in[6];
    const float* dec_w = (const float*)d_in[7];
    const float* dec_b = (const float*)d_in[8];
    float* out = (float*)d_out;

    // 1) encoder grouped conv -> g_h
    enc_conv_kernel<<<(BATCH * G_GROUPS) / 256, 256>>>(x, enc_w, enc_b);

    // 2) GEMM1: g_zp[s] = g_h[128,30000] * efc_w[2000,30000]^T  (k-split x9, 144 CTAs)
    {
        float* zp;  // device address of g_zp via kernel-visible symbol trick:
        // obtain address host-side once per call (non-stream API; capture-safe)
        cudaGetSymbolAddress((void**)&zp, g_zp);
        float* h;
        cudaGetSymbolAddress((void**)&h, g_h);
        gemm_tf32_kernel<0><<<dim3((LATDIM + BN - 1) / BN, KSPLIT1), GEMM_THREADS>>>(
            h, GC, efc_w, GC, zp, LATDIM, BATCH * LATDIM, nullptr, LATDIM, GC, KSPLIT_LEN1);
    }

    // 3) reduce splits + bias + leaky-relu -> g_z
    reduce_z_kernel<<<(BATCH * LATDIM) / 256, 256>>>(efc_b);

    // 4) GEMM2: g_d = lrelu(g_z[128,2000] * dfc_w[30000,2000]^T + bias)  (235 CTAs)
    {
        float* z;
        cudaGetSymbolAddress((void**)&z, g_z);
        float* d;
        cudaGetSymbolAddress((void**)&d, g_d);
        gemm_tf32_kernel<1><<<dim3((GC + BN - 1) / BN, 1), GEMM_THREADS>>>(
            z, LATDIM, dfc_w, LATDIM, d, GC, 0, dfc_b, GC, LATDIM, LATDIM);
    }

    // 5) decoder conv-transpose + sigmoid -> out
    dec_conv_kernel<<<(BATCH * G_GROUPS) / 256, 256>>>(dec_w, dec_b, out);
}

// round 11
// speedup vs baseline: 1.0199x; 1.0199x over previous
#include <cuda_runtime.h>
#include <cstdint>

// ---------------------------------------------------------------------------
// Problem constants
// ---------------------------------------------------------------------------
#define BATCH     128
#define G_GROUPS  10000
#define NCH       3
#define KWIN      20
#define LATDIM    2000
#define GC        30000      // G_GROUPS * NCH
#define INPUT_LEN 200000     // G_GROUPS * KWIN

// GEMM1 K-split: 18 splits of 1680 (multiple of 16 -> aligned cp.async),
// 17*1680 = 28560, last split = 1440 (also multiple of 16).
// 16 N-tiles * 18 splits = 288 CTAs (~148*2 = 296 slots -> ~2 CTAs/SM).
#define KSPLIT1      18
#define KSPLIT_LEN1  1680

// ---------------------------------------------------------------------------
// Device scratch (static __device__ arrays; no runtime allocation)
// ---------------------------------------------------------------------------
__device__ float g_h [BATCH * GC];                 // encoder conv output
__device__ float g_zp[KSPLIT1 * BATCH * LATDIM];   // GEMM1 partials (18.4 MB)
__device__ float g_z [BATCH * LATDIM];             // latent
__device__ float g_d [BATCH * GC];                 // decoder FC output

__device__ __forceinline__ float lrelu(float v) { return v > 0.f ? v : 0.1f * v; }

// ---------------------------------------------------------------------------
// Kernel 1: encoder grouped conv
//   g_h[b, g*3+c] = lrelu(dot(x[b, g*20:], enc_w[g,c,:]) + enc_b[g,c])
// ---------------------------------------------------------------------------
__global__ void enc_conv_kernel(const float* __restrict__ x,
                                const float* __restrict__ w,
                                const float* __restrict__ bias)
{
    int idx = blockIdx.x * blockDim.x + threadIdx.x;
    if (idx >= BATCH * G_GROUPS) return;
    int b = idx / G_GROUPS;
    int g = idx - b * G_GROUPS;

    const float4* xp = reinterpret_cast<const float4*>(x + (size_t)b * INPUT_LEN + (size_t)g * KWIN);
    float xr[KWIN];
#pragma unroll
    for (int i = 0; i < 5; ++i) {
        float4 v = __ldg(xp + i);
        xr[4*i+0] = v.x; xr[4*i+1] = v.y; xr[4*i+2] = v.z; xr[4*i+3] = v.w;
    }
    const float4* wp = reinterpret_cast<const float4*>(w + (size_t)g * (NCH * KWIN));
    float wr[NCH * KWIN];
#pragma unroll
    for (int i = 0; i < 15; ++i) {
        float4 v = __ldg(wp + i);
        wr[4*i+0] = v.x; wr[4*i+1] = v.y; wr[4*i+2] = v.z; wr[4*i+3] = v.w;
    }
    float acc[NCH];
#pragma unroll
    for (int c = 0; c < NCH; ++c) acc[c] = __ldg(bias + (size_t)g * NCH + c);
#pragma unroll
    for (int c = 0; c < NCH; ++c)
#pragma unroll
        for (int k = 0; k < KWIN; ++k)
            acc[c] = fmaf(xr[k], wr[c * KWIN + k], acc[c]);

    float* hp = g_h + (size_t)b * GC + (size_t)g * NCH;
#pragma unroll
    for (int c = 0; c < NCH; ++c) hp[c] = lrelu(acc[c]);
}

// ---------------------------------------------------------------------------
// TF32 tensor-core GEMM (mma.sync):  C[128, N] = A[128, K] * B[N, K]^T
//   CTA tile 128x128, K-chunk 16, 4-stage cp.async ring (80 KB dynamic smem).
//   EPI=0: write raw partial (per-k-split buffer);  EPI=1: +bias, leaky-relu.
// ---------------------------------------------------------------------------
#define BM 128
#define BN 128
#define BK 16
#define SSTR 20              // BK + 4 pad: conflict-free fragment LDS
#define STAGES 4
#define STAGE_FLOATS (2 * BM * SSTR)            // As + Bs per stage (20480 B)
#define GEMM_SMEM (STAGES * STAGE_FLOATS * 4)   // 81920 B
#define GEMM_THREADS 256

__device__ __forceinline__ uint32_t f2tf(float f) {
    uint32_t r;
    asm("cvt.rna.tf32.f32 %0, %1;" : "=r"(r) : "f"(f));
    return r;
}

__device__ __forceinline__ void cp16(float* sdst, const float* gsrc, int bytes) {
    uint32_t sa = static_cast<uint32_t>(__cvta_generic_to_shared(sdst));
    asm volatile("cp.async.cg.shared.global [%0], [%1], 16, %2;\n"
                 :: "r"(sa), "l"(gsrc), "r"(bytes));
}

template <int EPI>
__global__ void __launch_bounds__(GEMM_THREADS, 2)
gemm_tf32_kernel(const float* __restrict__ A, int ldA,
                 const float* __restrict__ Bm, int ldB,
                 float* __restrict__ Cbase, int ldC, int cSplitStride,
                 const float* __restrict__ bias,
                 int N, int K, int kSplitLen)
{
    extern __shared__ __align__(16) float smem[];

    const int tid  = threadIdx.x;
    const int n0   = blockIdx.x * BN;
    const int kBeg = blockIdx.y * kSplitLen;
    const int kEnd = min(K, kBeg + kSplitLen);
    float* C = Cbase + (size_t)blockIdx.y * cSplitStride;

    const int loadRow = tid >> 2;        // 0..63
    const int loadKq  = tid & 3;         // 4-float chunk within the 16-k row

    const int warp  = tid >> 5;
    const int lane  = tid & 31;
    const int g     = lane >> 2;
    const int tig   = lane & 3;
    const int wMoff = (warp & 3) * 32;   // 4 warps along M
    const int wNoff = (warp >> 2) * 64;  // 2 warps along N

    float acc[2][8][4];
#pragma unroll
    for (int mt = 0; mt < 2; ++mt)
#pragma unroll
        for (int nt = 0; nt < 8; ++nt)
#pragma unroll
            for (int i = 0; i < 4; ++i) acc[mt][nt][i] = 0.f;

    auto load_stage = [&](int st, int k0) {
        float* As = smem + st * STAGE_FLOATS;
        float* Bs = As + BM * SSTR;
#pragma unroll
        for (int j = 0; j < 2; ++j) {               // A tile: 128 x 16
            int row = loadRow + 64 * j;
            int k   = k0 + loadKq * 4;
            int bytes = (kEnd - k) * 4;             // 0 or 16 (aligned splits)
            bytes = bytes < 0 ? 0 : (bytes > 16 ? 16 : bytes);
            const float* gp = bytes > 0 ? (A + (size_t)row * ldA + k) : A;
            cp16(&As[row * SSTR + loadKq * 4], gp, bytes);
        }
#pragma unroll
        for (int j = 0; j < 2; ++j) {               // B tile: 128 x 16
            int row = loadRow + 64 * j;
            int n   = n0 + row;
            int k   = k0 + loadKq * 4;
            int bytes = (kEnd - k) * 4;
            bytes = bytes < 0 ? 0 : (bytes > 16 ? 16 : bytes);
            if (n >= N) bytes = 0;
            const float* gp = bytes > 0 ? (Bm + (size_t)n * ldB + k) : Bm;
            cp16(&Bs[row * SSTR + loadKq * 4], gp, bytes);
        }
    };

    const int nChunks = (kEnd - kBeg + BK - 1) / BK;

    // Prologue: commit exactly STAGES-1 groups (possibly empty) so that
    // wait_group(STAGES-2) in iteration c always certifies stage c.
#pragma unroll
    for (int s = 0; s < STAGES - 1; ++s) {
        if (s < nChunks) load_stage(s, kBeg + s * BK);
        asm volatile("cp.async.commit_group;\n" ::: "memory");
    }

#pragma unroll 1
    for (int c = 0; c < nChunks; ++c) {
        asm volatile("cp.async.wait_group %0;\n" :: "n"(STAGES - 2) : "memory");
        __syncthreads();

        // Refill the buffer freed at end of iteration c-1 with stage c+STAGES-1.
        if (c + STAGES - 1 < nChunks)
            load_stage((c + STAGES - 1) % STAGES, kBeg + (c + STAGES - 1) * BK);
        asm volatile("cp.async.commit_group;\n" ::: "memory");

        const float* As_ = smem + (c % STAGES) * STAGE_FLOATS;
        const float* Bs_ = As_ + BM * SSTR;
#pragma unroll
        for (int ks = 0; ks < BK / 8; ++ks) {
            const int kb = ks * 8;
            uint32_t af[2][4];
#pragma unroll
            for (int mt = 0; mt < 2; ++mt) {
                int r = wMoff + mt * 16 + g;
                af[mt][0] = f2tf(As_[(r    ) * SSTR + kb + tig    ]);
                af[mt][1] = f2tf(As_[(r + 8) * SSTR + kb + tig    ]);
                af[mt][2] = f2tf(As_[(r    ) * SSTR + kb + tig + 4]);
                af[mt][3] = f2tf(As_[(r + 8) * SSTR + kb + tig + 4]);
            }
            uint32_t bf[8][2];
#pragma unroll
            for (int nt = 0; nt < 8; ++nt) {
                int rn = wNoff + nt * 8 + g;
                bf[nt][0] = f2tf(Bs_[rn * SSTR + kb + tig    ]);
                bf[nt][1] = f2tf(Bs_[rn * SSTR + kb + tig + 4]);
            }
#pragma unroll
            for (int mt = 0; mt < 2; ++mt)
#pragma unroll
                for (int nt = 0; nt < 8; ++nt) {
                    asm volatile(
                        "mma.sync.aligned.m16n8k8.row.col.f32.tf32.tf32.f32 "
                        "{%0,%1,%2,%3}, {%4,%5,%6,%7}, {%8,%9}, {%0,%1,%2,%3};\n"
                        : "+f"(acc[mt][nt][0]), "+f"(acc[mt][nt][1]),
                          "+f"(acc[mt][nt][2]), "+f"(acc[mt][nt][3])
                        : "r"(af[mt][0]), "r"(af[mt][1]), "r"(af[mt][2]), "r"(af[mt][3]),
                          "r"(bf[nt][0]), "r"(bf[nt][1]));
                }
        }
        __syncthreads();
    }

    // Epilogue: c0,c1 -> (row, 2*tig[+1]); c2,c3 -> (row+8, ...)
#pragma unroll
    for (int mt = 0; mt < 2; ++mt) {
        int row0 = wMoff + mt * 16 + g;
#pragma unroll
        for (int nt = 0; nt < 8; ++nt) {
            int col = n0 + wNoff + nt * 8 + 2 * tig;
#pragma unroll
            for (int hh = 0; hh < 2; ++hh) {
                int row = row0 + 8 * hh;
#pragma unroll
                for (int q = 0; q < 2; ++q) {
                    int cc = col + q;
                    if (cc < N) {
                        float v = acc[mt][nt][hh * 2 + q];
                        if (EPI == 1) {
                            v += __ldg(bias + cc);
                            v = v > 0.f ? v : 0.1f * v;
                        }
                        C[(size_t)row * ldC + cc] = v;
                    }
                }
            }
        }
    }
}

// ---------------------------------------------------------------------------
// Kernel 3: reduce GEMM1 k-split partials + bias + leaky-relu -> g_z
// ---------------------------------------------------------------------------
__global__ void reduce_z_kernel(const float* __restrict__ bias)
{
    int i = blockIdx.x * blockDim.x + threadIdx.x;
    if (i >= BATCH * LATDIM) return;
    float s = __ldg(bias + (i % LATDIM));
#pragma unroll
    for (int p = 0; p < KSPLIT1; ++p) s += g_zp[(size_t)p * (BATCH * LATDIM) + i];
    g_z[i] = s > 0.f ? s : 0.1f * s;
}

// ---------------------------------------------------------------------------
// Kernel 5: decoder grouped conv-transpose + sigmoid
// ---------------------------------------------------------------------------
__global__ void dec_conv_kernel(const float* __restrict__ w,
                                const float* __restrict__ bias,
                                float* __restrict__ out)
{
    int idx = blockIdx.x * blockDim.x + threadIdx.x;
    if (idx >= BATCH * G_GROUPS) return;
    int b = idx / G_GROUPS;
    int g = idx - b * G_GROUPS;

    const float* dp = g_d + (size_t)b * GC + (size_t)g * NCH;
    float d0 = __ldg(dp + 0), d1 = __ldg(dp + 1), d2 = __ldg(dp + 2);

    float wr[NCH * KWIN];
    const float4* wp = reinterpret_cast<const float4*>(w + (size_t)g * (NCH * KWIN));
#pragma unroll
    for (int i = 0; i < 15; ++i) {
        float4 v = __ldg(wp + i);
        wr[4*i+0] = v.x; wr[4*i+1] = v.y; wr[4*i+2] = v.z; wr[4*i+3] = v.w;
    }
    float bg = __ldg(bias + g);

    float4* op = reinterpret_cast<float4*>(out + (size_t)b * INPUT_LEN + (size_t)g * KWIN);
#pragma unroll
    for (int i = 0; i < 5; ++i) {
        float4 o;
        float* of = reinterpret_cast<float*>(&o);
#pragma unroll
        for (int j = 0; j < 4; ++j) {
            int k = 4 * i + j;
            float v = bg;
            v = fmaf(d0, wr[k], v);
            v = fmaf(d1, wr[KWIN + k], v);
            v = fmaf(d2, wr[2 * KWIN + k], v);
            of[j] = 1.f / (1.f + __expf(-v));
        }
        op[i] = o;
    }
}

// ---------------------------------------------------------------------------
// Launch (graph-capturable: kernel launches only; attribute setup guarded)
// ---------------------------------------------------------------------------
extern "C" void kernel_launch(void* const* d_in, const int* in_sizes, int n_in,
                              void* d_out, int out_size)
{
    const float* x     = (const float*)d_in[0];
    const float* enc_w = (const float*)d_in[1];
    const float* enc_b = (const float*)d_in[2];
    const float* efc_w = (const float*)d_in[3];
    const float* efc_b = (const float*)d_in[4];
    const float* dfc_w = (const float*)d_in[5];
    const float* dfc_b = (const float*)d_in[6];
    const float* dec_w = (const float*)d_in[7];
    const float* dec_b = (const float*)d_in[8];
    float* out = (float*)d_out;

    // Opt in to >48KB dynamic smem once (host-side attribute, not a stream op).
    static bool attr_done = false;
    if (!attr_done) {
        cudaFuncSetAttribute(gemm_tf32_kernel<0>,
                             cudaFuncAttributeMaxDynamicSharedMemorySize, GEMM_SMEM);
        cudaFuncSetAttribute(gemm_tf32_kernel<1>,
                             cudaFuncAttributeMaxDynamicSharedMemorySize, GEMM_SMEM);
        attr_done = true;
    }

    float *h, *zp, *z, *d;
    cudaGetSymbolAddress((void**)&h,  g_h);
    cudaGetSymbolAddress((void**)&zp, g_zp);
    cudaGetSymbolAddress((void**)&z,  g_z);
    cudaGetSymbolAddress((void**)&d,  g_d);

    // 1) encoder grouped conv -> g_h
    enc_conv_kernel<<<(BATCH * G_GROUPS) / 256, 256>>>(x, enc_w, enc_b);

    // 2) GEMM1: g_zp[s] = g_h[128,30000] * efc_w[2000,30000]^T  (k-split x18, 288 CTAs)
    gemm_tf32_kernel<0><<<dim3((LATDIM + BN - 1) / BN, KSPLIT1), GEMM_THREADS, GEMM_SMEM>>>(
        h, GC, efc_w, GC, zp, LATDIM, BATCH * LATDIM, nullptr, LATDIM, GC, KSPLIT_LEN1);

    // 3) reduce splits + bias + leaky-relu -> g_z
    reduce_z_kernel<<<(BATCH * LATDIM) / 256, 256>>>(efc_b);

    // 4) GEMM2: g_d = lrelu(g_z[128,2000] * dfc_w[30000,2000]^T + bias)  (235 CTAs)
    gemm_tf32_kernel<1><<<dim3((GC + BN - 1) / BN, 1), GEMM_THREADS, GEMM_SMEM>>>(
        z, LATDIM, dfc_w, LATDIM, d, GC, 0, dfc_b, GC, LATDIM, LATDIM);

    // 5) decoder conv-transpose + sigmoid -> out
    dec_conv_kernel<<<(BATCH * G_GROUPS) / 256, 256>>>(dec_w, dec_b, out);
}